// round 3
// baseline (speedup 1.0000x reference)
#include <cuda_runtime.h>
#include <cuda_bf16.h>
#include <cstdint>
#include <cstddef>

// ============================================================================
// SigLIP loss: loss = sum(softplus(-labels * (scale*F@S^T + bias))) / N
// N=16384, D=512. compute_100 toolchain (no 'a') -> mma.sync bf16 GEMM.
// Tile 128x256, 512 threads (16 warps, 4m x 4n), 4-stage cp.async pipeline,
// fused softplus epilogue, atomic-free reduction via per-CTA partials.
// ============================================================================

#define N_ROWS 16384
#define D_DIM  512
#define BM 128
#define BN 256
#define BK 64
#define N_CHUNKS (D_DIM / BK)            // 8
#define STAGES 4
#define THREADS 512
#define A_BYTES (BM * BK * 2)            // 16 KB
#define B_BYTES (BN * BK * 2)            // 32 KB
#define STAGE_BYTES (A_BYTES + B_BYTES)  // 48 KB
#define A_SEGS (A_BYTES / 16)            // 1024
#define SEGS (STAGE_BYTES / 16)          // 3072
#define SMEM_DYN (STAGES * STAGE_BYTES + 1024)
#define GRID_X (N_ROWS / BN)             // 64
#define GRID_Y (N_ROWS / BM)             // 128
#define NPART (GRID_X * GRID_Y)          // 8192

__device__ __nv_bfloat16 g_F[(size_t)N_ROWS * D_DIM];
__device__ __nv_bfloat16 g_S[(size_t)N_ROWS * D_DIM];
__device__ float g_part[NPART];

// ---------------------------------------------------------------------------
__device__ __forceinline__ uint32_t smem_u32(const void* p) {
    uint32_t a;
    asm("{ .reg .u64 t; cvta.to.shared.u64 t, %1; cvt.u32.u64 %0, t; }"
        : "=r"(a) : "l"(p));
    return a;
}

__device__ __forceinline__ void cp_async16(uint32_t smem_addr, const void* gptr) {
    asm volatile("cp.async.cg.shared.global [%0], [%1], 16;"
                 :: "r"(smem_addr), "l"(gptr) : "memory");
}
#define CP_COMMIT() asm volatile("cp.async.commit_group;" ::: "memory")
#define CP_WAIT(n)  asm volatile("cp.async.wait_group %0;" :: "n"(n) : "memory")

// SW128-style swizzle (Swizzle<3,4,3>): conflict-free for 128B rows
__device__ __forceinline__ uint32_t swz(uint32_t off) {
    return off ^ ((off >> 3) & 0x70u);
}

__device__ __forceinline__ void ldsm_x4(uint32_t* r, uint32_t addr) {
    asm volatile("ldmatrix.sync.aligned.m8n8.x4.shared.b16 {%0,%1,%2,%3}, [%4];"
                 : "=r"(r[0]), "=r"(r[1]), "=r"(r[2]), "=r"(r[3]) : "r"(addr));
}

__device__ __forceinline__ void mma16816(float* d, const uint32_t* a,
                                         const uint32_t* b) {
    asm volatile(
        "mma.sync.aligned.m16n8k16.row.col.f32.bf16.bf16.f32 "
        "{%0,%1,%2,%3}, {%4,%5,%6,%7}, {%8,%9}, {%0,%1,%2,%3};"
        : "+f"(d[0]), "+f"(d[1]), "+f"(d[2]), "+f"(d[3])
        : "r"(a[0]), "r"(a[1]), "r"(a[2]), "r"(a[3]), "r"(b[0]), "r"(b[1]));
}

// ---------------------------------------------------------------------------
// Kernel 1: fp32 -> bf16 conversion of both feature matrices
// ---------------------------------------------------------------------------
__global__ void cvt_kernel(const float* __restrict__ F, const float* __restrict__ S) {
    size_t i = (size_t)blockIdx.x * 256 + threadIdx.x;
    if (i >= (size_t)N_ROWS * D_DIM / 4) return;
    float4 f = reinterpret_cast<const float4*>(F)[i];
    float4 s = reinterpret_cast<const float4*>(S)[i];
    __nv_bfloat162 f01 = __floats2bfloat162_rn(f.x, f.y);
    __nv_bfloat162 f23 = __floats2bfloat162_rn(f.z, f.w);
    __nv_bfloat162 s01 = __floats2bfloat162_rn(s.x, s.y);
    __nv_bfloat162 s23 = __floats2bfloat162_rn(s.z, s.w);
    uint2 fo, so;
    fo.x = *reinterpret_cast<uint32_t*>(&f01);
    fo.y = *reinterpret_cast<uint32_t*>(&f23);
    so.x = *reinterpret_cast<uint32_t*>(&s01);
    so.y = *reinterpret_cast<uint32_t*>(&s23);
    reinterpret_cast<uint2*>(g_F)[i] = fo;
    reinterpret_cast<uint2*>(g_S)[i] = so;
}

// ---------------------------------------------------------------------------
// Kernel 2: 128x256xK512 GEMM tile + fused softplus reduction
//   grid = (64, 128): x -> column tile (BN), y -> row tile (BM)
//   16 warps as 4 (m) x 4 (n); warp tile 32x64; mma m16n8k16 bf16
// ---------------------------------------------------------------------------
__global__ void __launch_bounds__(THREADS, 1) gemm_loss_kernel(
    const int* __restrict__ first_label, const int* __restrict__ second_label,
    const float* __restrict__ scale_p, const float* __restrict__ bias_p)
{
    extern __shared__ char smem[];
    __shared__ int   s_flbl[BM];
    __shared__ int   s_slbl[BN];
    __shared__ float s_red[16];

    const uint32_t sbase = smem_u32(smem);
    const uint32_t tb = (sbase + 1023u) & ~1023u;   // 1024-aligned tile base
    const int tid = threadIdx.x;
    const int wid = tid >> 5;
    const int lane = tid & 31;
    const int warp_m = wid & 3;      // 0..3 -> 32-row slice
    const int warp_n = wid >> 2;     // 0..3 -> 64-col slice
    const int row0 = blockIdx.y * BM;
    const int col0 = blockIdx.x * BN;

    if (tid < BM)                 s_flbl[tid] = first_label[row0 + tid];
    else if (tid < BM + BN)       s_slbl[tid - BM] = second_label[col0 + tid - BM];

    const __nv_bfloat16* gA0 = g_F + (size_t)row0 * D_DIM;
    const __nv_bfloat16* gB0 = g_S + (size_t)col0 * D_DIM;

    // seg s: s<1024 -> A (r=s>>3), else B (t=s-1024, r=t>>3); c = s&7 (16B col)
    auto load_chunk = [&](int k, int st) {
        const uint32_t base = tb + (uint32_t)st * STAGE_BYTES;
        const int kofs = k * BK;
        #pragma unroll
        for (int i = 0; i < SEGS / THREADS; ++i) {      // 6 segs per thread
            const int s = tid + i * THREADS;
            const int c = s & 7;
            if (s < A_SEGS) {
                const int r = s >> 3;
                const uint32_t off = (uint32_t)(r * 128 + c * 16);
                cp_async16(base + swz(off), gA0 + (size_t)r * D_DIM + kofs + c * 8);
            } else {
                const int r = (s - A_SEGS) >> 3;
                const uint32_t off = (uint32_t)(r * 128 + c * 16);
                cp_async16(base + A_BYTES + swz(off),
                           gB0 + (size_t)r * D_DIM + kofs + c * 8);
            }
        }
        CP_COMMIT();
    };

    // accumulators: 2 m-tiles x 8 n-tiles x 4 regs (warp tile 32x64)
    float acc[2][8][4];
    #pragma unroll
    for (int mt = 0; mt < 2; ++mt)
        #pragma unroll
        for (int nt = 0; nt < 8; ++nt)
            #pragma unroll
            for (int i = 0; i < 4; ++i) acc[mt][nt][i] = 0.0f;

    // ldmatrix lane address components (CTA-tile relative)
    const uint32_t aRowOff = (uint32_t)((warp_m * 32 + (lane & 15)) * 128 +
                                        ((lane >> 4) * 16));
    const uint32_t bRowOff = (uint32_t)((warp_n * 64 + (lane & 7) +
                                         ((lane >> 4) << 3)) * 128 +
                                        (((lane >> 3) & 1) << 4));

    auto compute_chunk = [&](int st) {
        const uint32_t aBase = tb + (uint32_t)st * STAGE_BYTES;
        const uint32_t bBase = aBase + A_BYTES;
        #pragma unroll
        for (int ks = 0; ks < 4; ++ks) {          // 4 x k16 steps in BK=64
            const uint32_t kb = (uint32_t)(ks * 32);
            uint32_t af[2][4], bf[4][4];
            #pragma unroll
            for (int mt = 0; mt < 2; ++mt)
                ldsm_x4(af[mt], aBase + swz(aRowOff + (uint32_t)(mt * 16 * 128) + kb));
            #pragma unroll
            for (int bt = 0; bt < 4; ++bt)
                ldsm_x4(bf[bt], bBase + swz(bRowOff + (uint32_t)(bt * 16 * 128) + kb));
            #pragma unroll
            for (int mt = 0; mt < 2; ++mt)
                #pragma unroll
                for (int nt = 0; nt < 8; ++nt)
                    mma16816(acc[mt][nt], af[mt], &bf[nt >> 1][(nt & 1) * 2]);
        }
    };

    load_chunk(0, 0);
    load_chunk(1, 1);
    load_chunk(2, 2);

    #pragma unroll
    for (int k = 0; k < N_CHUNKS; ++k) {
        // exact tail waits: after the last load, fewer groups remain in flight
        if (k < N_CHUNKS - 3)      { CP_WAIT(2); }
        else if (k == N_CHUNKS - 3){ CP_WAIT(2); }
        else if (k == N_CHUNKS - 2){ CP_WAIT(1); }
        else                       { CP_WAIT(0); }
        __syncthreads();
        compute_chunk(k % STAGES);
        if (k + 3 < N_CHUNKS) load_chunk(k + 3, (k + 3) % STAGES);
    }

    // ------------------ epilogue: softplus + reduce ------------------
    const float scale = *scale_p;
    const float bias  = *bias_p;
    float lsum = 0.0f;

    #pragma unroll
    for (int mt = 0; mt < 2; ++mt) {
        const int rbase = warp_m * 32 + mt * 16 + (lane >> 2);
        const int fl0 = s_flbl[rbase];
        const int fl1 = s_flbl[rbase + 8];
        #pragma unroll
        for (int nt = 0; nt < 8; ++nt) {
            const int cbase = warp_n * 64 + nt * 8 + (lane & 3) * 2;
            const int sl0 = s_slbl[cbase];
            const int sl1 = s_slbl[cbase + 1];
            #pragma unroll
            for (int i = 0; i < 4; ++i) {
                const int fl = (i < 2) ? fl0 : fl1;
                const int sl = (i & 1) ? sl1 : sl0;
                const float logit = fmaf(scale, acc[mt][nt][i], bias);
                // label +1 (match) -> softplus(-logit); else softplus(+logit)
                const float x = (sl == fl) ? -logit : logit;
                const float a = fabsf(x);
                lsum += fmaxf(x, 0.0f) + __logf(1.0f + __expf(-a));
            }
        }
    }

    #pragma unroll
    for (int o = 16; o; o >>= 1) lsum += __shfl_xor_sync(0xffffffffu, lsum, o);
    if (lane == 0) s_red[wid] = lsum;
    __syncthreads();
    if (tid == 0) {
        float cs = 0.0f;
        #pragma unroll
        for (int i = 0; i < 16; ++i) cs += s_red[i];
        g_part[blockIdx.y * GRID_X + blockIdx.x] = cs;
    }
}

// ---------------------------------------------------------------------------
// Kernel 3: finalize (atomic-free deterministic reduction)
// ---------------------------------------------------------------------------
__global__ void finalize_kernel(float* __restrict__ out) {
    __shared__ double sd[256];
    double s = 0.0;
    for (int i = threadIdx.x; i < NPART; i += 256) s += (double)g_part[i];
    sd[threadIdx.x] = s;
    __syncthreads();
    #pragma unroll
    for (int o = 128; o; o >>= 1) {
        if (threadIdx.x < o) sd[threadIdx.x] += sd[threadIdx.x + o];
        __syncthreads();
    }
    if (threadIdx.x == 0) out[0] = (float)(sd[0] * (1.0 / (double)N_ROWS));
}

// ---------------------------------------------------------------------------
extern "C" void kernel_launch(void* const* d_in, const int* in_sizes, int n_in,
                              void* d_out, int out_size)
{
    const float* F  = (const float*)d_in[0];
    const float* S  = (const float*)d_in[1];
    const int*   l1 = (const int*)d_in[2];
    const int*   l2 = (const int*)d_in[3];
    const float* sc = (const float*)d_in[4];
    const float* bi = (const float*)d_in[5];

    cudaFuncSetAttribute((const void*)gemm_loss_kernel,
                         cudaFuncAttributeMaxDynamicSharedMemorySize, SMEM_DYN);

    const int n4blocks = (int)(((size_t)N_ROWS * D_DIM / 4 + 255) / 256);
    cvt_kernel<<<n4blocks, 256>>>(F, S);
    gemm_loss_kernel<<<dim3(GRID_X, GRID_Y), THREADS, SMEM_DYN>>>(l1, l2, sc, bi);
    finalize_kernel<<<1, 256>>>((float*)d_out);
}

// round 4
// speedup vs baseline: 1.0601x; 1.0601x over previous
#include <cuda_runtime.h>
#include <cuda_bf16.h>
#include <cstdint>
#include <cstddef>

// ============================================================================
// SigLIP loss: loss = sum(softplus(-labels * (scale*F@S^T + bias))) / N
// N=16384, D=512. compute_100 toolchain (no 'a') -> mma.sync bf16 GEMM.
// Tile 128x128, 256 threads (8 warps, 4m x 2n), 3-stage cp.async pipeline,
// 2 CTAs/SM for mainloop/epilogue overlap, fused poly-softplus epilogue,
// atomic-free reduction via per-CTA partials.
// ============================================================================

#define N_ROWS 16384
#define D_DIM  512
#define BM 128
#define BN 128
#define BK 64
#define N_CHUNKS (D_DIM / BK)            // 8
#define STAGES 3
#define THREADS 256
#define A_BYTES (BM * BK * 2)            // 16 KB
#define B_BYTES (BN * BK * 2)            // 16 KB
#define STAGE_BYTES (A_BYTES + B_BYTES)  // 32 KB
#define A_SEGS (A_BYTES / 16)            // 1024
#define SEGS (STAGE_BYTES / 16)          // 2048
#define SMEM_DYN (STAGES * STAGE_BYTES + 1024)
#define GRID_X (N_ROWS / BN)             // 128
#define GRID_Y (N_ROWS / BM)             // 128
#define NPART (GRID_X * GRID_Y)          // 16384

__device__ __nv_bfloat16 g_F[(size_t)N_ROWS * D_DIM];
__device__ __nv_bfloat16 g_S[(size_t)N_ROWS * D_DIM];
__device__ float g_part[NPART];

// ---------------------------------------------------------------------------
__device__ __forceinline__ uint32_t smem_u32(const void* p) {
    uint32_t a;
    asm("{ .reg .u64 t; cvta.to.shared.u64 t, %1; cvt.u32.u64 %0, t; }"
        : "=r"(a) : "l"(p));
    return a;
}

__device__ __forceinline__ void cp_async16(uint32_t smem_addr, const void* gptr) {
    asm volatile("cp.async.cg.shared.global [%0], [%1], 16;"
                 :: "r"(smem_addr), "l"(gptr) : "memory");
}
#define CP_COMMIT() asm volatile("cp.async.commit_group;" ::: "memory")
#define CP_WAIT(n)  asm volatile("cp.async.wait_group %0;" :: "n"(n) : "memory")

// SW128-style swizzle (Swizzle<3,4,3>): conflict-free for 128B rows
__device__ __forceinline__ uint32_t swz(uint32_t off) {
    return off ^ ((off >> 3) & 0x70u);
}

__device__ __forceinline__ void ldsm_x4(uint32_t* r, uint32_t addr) {
    asm volatile("ldmatrix.sync.aligned.m8n8.x4.shared.b16 {%0,%1,%2,%3}, [%4];"
                 : "=r"(r[0]), "=r"(r[1]), "=r"(r[2]), "=r"(r[3]) : "r"(addr));
}

__device__ __forceinline__ void mma16816(float* d, const uint32_t* a,
                                         const uint32_t* b) {
    asm volatile(
        "mma.sync.aligned.m16n8k16.row.col.f32.bf16.bf16.f32 "
        "{%0,%1,%2,%3}, {%4,%5,%6,%7}, {%8,%9}, {%0,%1,%2,%3};"
        : "+f"(d[0]), "+f"(d[1]), "+f"(d[2]), "+f"(d[3])
        : "r"(a[0]), "r"(a[1]), "r"(a[2]), "r"(a[3]), "r"(b[0]), "r"(b[1]));
}

// ---------------------------------------------------------------------------
// Kernel 1: fp32 -> bf16 conversion of both feature matrices
// ---------------------------------------------------------------------------
__global__ void cvt_kernel(const float* __restrict__ F, const float* __restrict__ S) {
    size_t i = (size_t)blockIdx.x * 256 + threadIdx.x;
    if (i >= (size_t)N_ROWS * D_DIM / 4) return;
    float4 f = reinterpret_cast<const float4*>(F)[i];
    float4 s = reinterpret_cast<const float4*>(S)[i];
    __nv_bfloat162 f01 = __floats2bfloat162_rn(f.x, f.y);
    __nv_bfloat162 f23 = __floats2bfloat162_rn(f.z, f.w);
    __nv_bfloat162 s01 = __floats2bfloat162_rn(s.x, s.y);
    __nv_bfloat162 s23 = __floats2bfloat162_rn(s.z, s.w);
    uint2 fo, so;
    fo.x = *reinterpret_cast<uint32_t*>(&f01);
    fo.y = *reinterpret_cast<uint32_t*>(&f23);
    so.x = *reinterpret_cast<uint32_t*>(&s01);
    so.y = *reinterpret_cast<uint32_t*>(&s23);
    reinterpret_cast<uint2*>(g_F)[i] = fo;
    reinterpret_cast<uint2*>(g_S)[i] = so;
}

// ---------------------------------------------------------------------------
// Kernel 2: 128x128xK512 GEMM tile + fused softplus reduction
//   grid = (128, 128); 8 warps as 4 (m) x 2 (n); warp tile 32x64
// ---------------------------------------------------------------------------
__global__ void __launch_bounds__(THREADS, 2) gemm_loss_kernel(
    const int* __restrict__ first_label, const int* __restrict__ second_label,
    const float* __restrict__ scale_p, const float* __restrict__ bias_p)
{
    extern __shared__ char smem[];
    __shared__ int   s_flbl[BM];
    __shared__ int   s_slbl[BN];
    __shared__ float s_red[8];

    const uint32_t sbase = smem_u32(smem);
    const uint32_t tb = (sbase + 1023u) & ~1023u;   // 1024-aligned tile base
    const int tid = threadIdx.x;
    const int wid = tid >> 5;
    const int lane = tid & 31;
    const int warp_m = wid & 3;      // 0..3 -> 32-row slice
    const int warp_n = wid >> 2;     // 0..1 -> 64-col slice
    const int row0 = blockIdx.y * BM;
    const int col0 = blockIdx.x * BN;

    if (tid < BM) {
        s_flbl[tid] = first_label[row0 + tid];
        s_slbl[tid] = second_label[col0 + tid];
    }

    const __nv_bfloat16* gA0 = g_F + (size_t)row0 * D_DIM;
    const __nv_bfloat16* gB0 = g_S + (size_t)col0 * D_DIM;

    // seg s (0..2047): s<1024 -> A, else B; r = (s&1023)>>3 ; c = s&7 (16B col)
    auto load_chunk = [&](int k, int st) {
        const uint32_t base = tb + (uint32_t)st * STAGE_BYTES;
        const int kofs = k * BK;
        #pragma unroll
        for (int i = 0; i < SEGS / THREADS; ++i) {      // 8 segs per thread
            const int s = tid + i * THREADS;
            const int r = (s & 1023) >> 3;
            const int c = s & 7;
            const uint32_t off = (uint32_t)(r * 128 + c * 16);
            if (s < A_SEGS) {
                cp_async16(base + swz(off), gA0 + (size_t)r * D_DIM + kofs + c * 8);
            } else {
                cp_async16(base + A_BYTES + swz(off),
                           gB0 + (size_t)r * D_DIM + kofs + c * 8);
            }
        }
        CP_COMMIT();
    };

    // accumulators: 2 m-tiles x 8 n-tiles x 4 regs (warp tile 32x64)
    float acc[2][8][4];
    #pragma unroll
    for (int mt = 0; mt < 2; ++mt)
        #pragma unroll
        for (int nt = 0; nt < 8; ++nt)
            #pragma unroll
            for (int i = 0; i < 4; ++i) acc[mt][nt][i] = 0.0f;

    // ldmatrix lane address components (CTA-tile relative)
    const uint32_t aRowOff = (uint32_t)((warp_m * 32 + (lane & 15)) * 128 +
                                        ((lane >> 4) * 16));
    const uint32_t bRowOff = (uint32_t)((warp_n * 64 + (lane & 7) +
                                         ((lane >> 4) << 3)) * 128 +
                                        (((lane >> 3) & 1) << 4));

    auto compute_chunk = [&](int st) {
        const uint32_t aBase = tb + (uint32_t)st * STAGE_BYTES;
        const uint32_t bBase = aBase + A_BYTES;
        #pragma unroll
        for (int ks = 0; ks < 4; ++ks) {          // 4 x k16 steps in BK=64
            const uint32_t kb = (uint32_t)(ks * 32);
            uint32_t af[2][4], bf[4][4];
            #pragma unroll
            for (int mt = 0; mt < 2; ++mt)
                ldsm_x4(af[mt], aBase + swz(aRowOff + (uint32_t)(mt * 16 * 128) + kb));
            #pragma unroll
            for (int bt = 0; bt < 4; ++bt)
                ldsm_x4(bf[bt], bBase + swz(bRowOff + (uint32_t)(bt * 16 * 128) + kb));
            #pragma unroll
            for (int mt = 0; mt < 2; ++mt)
                #pragma unroll
                for (int nt = 0; nt < 8; ++nt)
                    mma16816(acc[mt][nt], af[mt], &bf[nt >> 1][(nt & 1) * 2]);
        }
    };

    load_chunk(0, 0);
    load_chunk(1, 1);

    #pragma unroll
    for (int k = 0; k < N_CHUNKS; ++k) {
        // committed groups at this point: 2 + min(k,6); chunk k must be landed
        if (k == N_CHUNKS - 1) { CP_WAIT(0); }
        else                   { CP_WAIT(1); }
        __syncthreads();
        // issue the next loads BEFORE compute so they fly during the MMAs;
        // stage (k+2)%3 == (k-1)%3 was released by the barrier above
        if (k + 2 < N_CHUNKS) load_chunk(k + 2, (k + 2) % STAGES);
        compute_chunk(k % STAGES);
    }

    // ------------------ epilogue: poly softplus + reduce ------------------
    // softplus(x) = max(x,0) + log1p(e^{-|x|});  y = e^{-a}, y in (0,1]
    // log1p(y) ~= y*(c0 + c1 y + c2 y^2 + c3 y^3), max abs err ~5e-4
    const float scale = *scale_p;
    const float bias  = *bias_p;
    const float c0 = 0.9995513f, c1 = -0.4831560f, c2 = 0.2462820f, c3 = -0.0693310f;
    float lsum = 0.0f;

    #pragma unroll
    for (int mt = 0; mt < 2; ++mt) {
        const int rbase = warp_m * 32 + mt * 16 + (lane >> 2);
        const int fl0 = s_flbl[rbase];
        const int fl1 = s_flbl[rbase + 8];
        #pragma unroll
        for (int nt = 0; nt < 8; ++nt) {
            const int cbase = warp_n * 64 + nt * 8 + (lane & 3) * 2;
            const int sl0 = s_slbl[cbase];
            const int sl1 = s_slbl[cbase + 1];
            #pragma unroll
            for (int i = 0; i < 4; ++i) {
                const int fl = (i < 2) ? fl0 : fl1;
                const int sl = (i & 1) ? sl1 : sl0;
                const float logit = fmaf(scale, acc[mt][nt][i], bias);
                // label +1 (match) -> softplus(-logit); else softplus(+logit)
                const float x = (sl == fl) ? -logit : logit;
                const float a = fabsf(x);
                const float y = __expf(-a);
                const float p = y * fmaf(y, fmaf(y, fmaf(y, c3, c2), c1), c0);
                lsum += fmaxf(x, 0.0f) + p;
            }
        }
    }

    #pragma unroll
    for (int o = 16; o; o >>= 1) lsum += __shfl_xor_sync(0xffffffffu, lsum, o);
    if (lane == 0) s_red[wid] = lsum;
    __syncthreads();
    if (tid == 0) {
        float cs = 0.0f;
        #pragma unroll
        for (int i = 0; i < 8; ++i) cs += s_red[i];
        g_part[blockIdx.y * GRID_X + blockIdx.x] = cs;
    }
}

// ---------------------------------------------------------------------------
// Kernel 3: finalize (atomic-free deterministic reduction)
// ---------------------------------------------------------------------------
__global__ void finalize_kernel(float* __restrict__ out) {
    __shared__ double sd[256];
    double s = 0.0;
    for (int i = threadIdx.x; i < NPART; i += 256) s += (double)g_part[i];
    sd[threadIdx.x] = s;
    __syncthreads();
    #pragma unroll
    for (int o = 128; o; o >>= 1) {
        if (threadIdx.x < o) sd[threadIdx.x] += sd[threadIdx.x + o];
        __syncthreads();
    }
    if (threadIdx.x == 0) out[0] = (float)(sd[0] * (1.0 / (double)N_ROWS));
}

// ---------------------------------------------------------------------------
extern "C" void kernel_launch(void* const* d_in, const int* in_sizes, int n_in,
                              void* d_out, int out_size)
{
    const float* F  = (const float*)d_in[0];
    const float* S  = (const float*)d_in[1];
    const int*   l1 = (const int*)d_in[2];
    const int*   l2 = (const int*)d_in[3];
    const float* sc = (const float*)d_in[4];
    const float* bi = (const float*)d_in[5];

    cudaFuncSetAttribute((const void*)gemm_loss_kernel,
                         cudaFuncAttributeMaxDynamicSharedMemorySize, SMEM_DYN);

    const int n4blocks = (int)(((size_t)N_ROWS * D_DIM / 4 + 255) / 256);
    cvt_kernel<<<n4blocks, 256>>>(F, S);
    gemm_loss_kernel<<<dim3(GRID_X, GRID_Y), THREADS, SMEM_DYN>>>(l1, l2, sc, bi);
    finalize_kernel<<<1, 256>>>((float*)d_out);
}